// round 1
// baseline (speedup 1.0000x reference)
#include <cuda_runtime.h>
#include <stdint.h>

// Problem constants (fixed shape variant): B=1, H=8, D=64.
#define H 8
#define D 64

// Scratch: N*H entries needed (800k). Sized 4M for headroom. Allocation-free.
static __device__ float        g_attn[1 << 22];  // tanh(attn[n,h])
static __device__ unsigned int g_m   [1 << 22];  // transformed-uint running max per (target,h)

// Monotone float->uint transform: preserves ordering under unsigned compare.
__device__ __forceinline__ unsigned int f2key(float f) {
    unsigned int u = __float_as_uint(f);
    return (u & 0x80000000u) ? ~u : (u | 0x80000000u);
}
__device__ __forceinline__ float key2f(unsigned int k) {
    unsigned int u = (k & 0x80000000u) ? (k ^ 0x80000000u) : ~k;
    return __uint_as_float(u);
}

// K1: one warp per (n,h). 32 lanes each load float2 (64 floats = one 256B
// coalesced row of X), FMA with W[d,h], butterfly-reduce, lane 0 writes
// tanh(result) and zero-inits g_m at the same index. HBM-bound on X.
__global__ void k1_attn(const float* __restrict__ X, const float* __restrict__ Wk, int NH) {
    int gw   = (blockIdx.x * blockDim.x + threadIdx.x) >> 5;
    int lane = threadIdx.x & 31;
    if (gw >= NH) return;
    int h = gw & (H - 1);
    const float2* xr = (const float2*)(X + (size_t)gw * D);
    float2 v = xr[lane];
    float w0 = __ldg(&Wk[(2 * lane)     * H + h]);
    float w1 = __ldg(&Wk[(2 * lane + 1) * H + h]);
    float s = v.x * w0 + v.y * w1;
    #pragma unroll
    for (int o = 16; o > 0; o >>= 1) s += __shfl_xor_sync(0xffffffffu, s, o);
    if (lane == 0) {
        g_attn[gw] = tanhf(s);
        g_m[gw]    = 0u;   // key-space -inf (< any real key); re-init every call
    }
}

// K2: one thread per edge. Gather 8 tanhattn values (L2-resident 3.2MB table),
// transform to keys, atomicMax into m[target*8+h]. Read-check first: stale-low
// reads only cost an extra atomic, never correctness. Cuts atomic count ~8x.
__global__ void k2_max(const int* __restrict__ src, const int* __restrict__ tgt, int E) {
    int i = blockIdx.x * blockDim.x + threadIdx.x;
    if (i >= E) return;
    int s = src[i], t = tgt[i];
    const float*  av = g_attn + (size_t)s * H;
    unsigned int* mv = g_m    + (size_t)t * H;
    #pragma unroll
    for (int h = 0; h < H; h++) {
        unsigned int key = f2key(av[h]);
        unsigned int cur = mv[h];          // racy read: may be stale-low, fine
        if (key > cur) atomicMax(&mv[h], key);
    }
}

// K3: one thread per edge, float4-vectorized drop_mask read + output write.
// out[i,h] = exp(tanhattn[src,h] - m[tgt,h]) * drop_mask[i,h].
// (Denominator s == 1.0f exactly in fp32 — see analysis — so no division.)
__global__ void k3_out(const int* __restrict__ src, const int* __restrict__ tgt,
                       const float* __restrict__ drop, float* __restrict__ out, int E) {
    int i = blockIdx.x * blockDim.x + threadIdx.x;
    if (i >= E) return;
    int s = src[i], t = tgt[i];
    const float*        av = g_attn + (size_t)s * H;
    const unsigned int* mv = g_m    + (size_t)t * H;
    const float4* dr = (const float4*)(drop + (size_t)i * H);
    float4 d0 = dr[0], d1 = dr[1];
    float r[H];
    #pragma unroll
    for (int h = 0; h < H; h++) {
        float m = key2f(mv[h]);
        r[h] = __expf(av[h] - m);          // arg in [-2, 0]; __expf plenty accurate
    }
    float4 o0 = make_float4(r[0] * d0.x, r[1] * d0.y, r[2] * d0.z, r[3] * d0.w);
    float4 o1 = make_float4(r[4] * d1.x, r[5] * d1.y, r[6] * d1.z, r[7] * d1.w);
    float4* op = (float4*)(out + (size_t)i * H);
    op[0] = o0;
    op[1] = o1;
}

// Inputs (metadata order): 0:X(f32 B*N*H*D) 1:attn_kernel(f32 D*H*1)
// 2:targets(i32 B*E) 3:sources(i32 B*E) 4:degree(f32 B*N, unused)
// 5:drop_mask(f32 B*E*H) 6:N(scalar). Output: f32 B*E*H*1.
extern "C" void kernel_launch(void* const* d_in, const int* in_sizes, int n_in,
                              void* d_out, int out_size) {
    const float* X    = (const float*)d_in[0];
    const float* Wk   = (const float*)d_in[1];
    const int*   tgt  = (const int*)d_in[2];
    const int*   srcs = (const int*)d_in[3];
    const float* drop = (const float*)d_in[5];
    float*       out  = (float*)d_out;

    const int E = in_sizes[2];        // B*E, B=1
    const int N = in_sizes[4];        // B*N, B=1 (degree length)
    const int NH = N * H;

    // K1: NH warps -> NH*32 threads
    {
        long long threads = (long long)NH * 32;
        int block = 256;
        int grid  = (int)((threads + block - 1) / block);
        k1_attn<<<grid, block>>>(X, Wk, NH);
    }
    // K2: E threads
    {
        int block = 256;
        int grid  = (E + block - 1) / block;
        k2_max<<<grid, block>>>(srcs, tgt, E);
    }
    // K3: E threads
    {
        int block = 256;
        int grid  = (E + block - 1) / block;
        k3_out<<<grid, tgt ? block : block>>>(srcs, tgt, drop, out, E);
    }
}

// round 2
// speedup vs baseline: 2.5385x; 2.5385x over previous
#include <cuda_runtime.h>
#include <stdint.h>

// Fixed shape family: B=1, H=8, D=64. N, E read from in_sizes at launch.
#define H 8
#define D 64

// Scratch (allocation-free): N*H entries needed (800k typical). 4M headroom.
static __device__ float        g_attn[1 << 22];  // tanh(attn[n,h])
static __device__ unsigned int g_m   [1 << 22];  // transformed-uint running max per (target,h)

// Monotone float->uint transform (order-preserving under unsigned compare).
__device__ __forceinline__ unsigned int f2key(unsigned int u) {
    return (u & 0x80000000u) ? ~u : (u | 0x80000000u);
}
__device__ __forceinline__ float key2f(unsigned int k) {
    unsigned int u = (k & 0x80000000u) ? (k ^ 0x80000000u) : ~k;
    return __uint_as_float(u);
}

// Fast tanh via hardware exp (MUFU.EX2): rel err ~1e-7, far inside tolerance.
__device__ __forceinline__ float fast_tanh(float x) {
    float e = __expf(2.0f * x);
    return 1.0f - __fdividef(2.0f, e + 1.0f);
}

// ── K1: warp per row n. Row = H*D = 512 floats = 2KB, loaded as 4 coalesced
// LDG.128 per lane (float4 index lane + 32k). Element f = 4l+128k+j maps to
// h = 2k + (l>>4), d = 4*(l&15)+j. W[d][h] preloaded into 16 regs ONCE per
// warp (amortized over the grid-stride loop) — kills the 32-sector W loads
// that made R1's K1 L1-bound. Butterfly-reduce within each 16-lane half.
__global__ void k1_attn(const float4* __restrict__ X4, const float* __restrict__ Wk,
                        int N, int totalWarps) {
    int wid  = (blockIdx.x * blockDim.x + threadIdx.x) >> 5;
    int lane = threadIdx.x & 31;
    int lo = lane & 15, hi = lane >> 4;

    float w[4][4];
    #pragma unroll
    for (int k = 0; k < 4; k++)
        #pragma unroll
        for (int j = 0; j < 4; j++)
            w[k][j] = Wk[(4 * lo + j) * H + 2 * k + hi];

    for (int n = wid; n < N; n += totalWarps) {
        const float4* row = X4 + (size_t)n * (H * D / 4);
        float s[4];
        #pragma unroll
        for (int k = 0; k < 4; k++) {
            float4 v = row[lane + 32 * k];
            s[k] = v.x * w[k][0] + v.y * w[k][1] + v.z * w[k][2] + v.w * w[k][3];
        }
        #pragma unroll
        for (int o = 8; o >= 1; o >>= 1) {
            #pragma unroll
            for (int k = 0; k < 4; k++)
                s[k] += __shfl_xor_sync(0xffffffffu, s[k], o);
        }
        if (lo == 0) {
            float* ar = g_attn + (size_t)n * H;
            #pragma unroll
            for (int k = 0; k < 4; k++) ar[2 * k + hi] = fast_tanh(s[k]);
            if (hi == 0) {                     // re-init m keys every call
                uint4 z = make_uint4(0u, 0u, 0u, 0u);
                *(uint4*)(g_m + (size_t)n * H)     = z;
                *(uint4*)(g_m + (size_t)n * H + 4) = z;
            }
        }
    }
}

// ── K2: thread per edge. Vectorized 32B gathers of the attn row and the m
// row (2x uint4 each instead of 8 scalars -> 4x fewer L2 requests). Racy
// read-filter before atomicMax: stale-low reads only cost an extra atomic.
__global__ void k2_max(const int* __restrict__ src, const int* __restrict__ tgt, int E) {
    int i = blockIdx.x * blockDim.x + threadIdx.x;
    if (i >= E) return;
    int s = src[i], t = tgt[i];
    const uint4* av = (const uint4*)(g_attn + (size_t)s * H);
    uint4 a0 = av[0], a1 = av[1];
    unsigned int key[H] = { f2key(a0.x), f2key(a0.y), f2key(a0.z), f2key(a0.w),
                            f2key(a1.x), f2key(a1.y), f2key(a1.z), f2key(a1.w) };
    unsigned int* mv = g_m + (size_t)t * H;
    const uint4* mvv = (const uint4*)mv;
    uint4 m0 = mvv[0], m1 = mvv[1];
    unsigned int cur[H] = { m0.x, m0.y, m0.z, m0.w, m1.x, m1.y, m1.z, m1.w };
    #pragma unroll
    for (int h = 0; h < H; h++)
        if (key[h] > cur[h]) atomicMax(&mv[h], key[h]);
}

// ── K3: thread per edge. out[i,h] = exp(attn[src,h] - m[tgt,h]) * drop[i,h].
// (Denominator segment_max(exp(e-m)) + 1e-9 == 1.0f exactly in fp32: every
// segment attains exp(0)=1 and 1e-9 underflows the ulp of 1.0.) Fully
// vectorized: 32B gathers + 32B streaming drop read + 32B streaming store.
__global__ void k3_out(const int* __restrict__ src, const int* __restrict__ tgt,
                       const float4* __restrict__ drop4, float4* __restrict__ out4, int E) {
    int i = blockIdx.x * blockDim.x + threadIdx.x;
    if (i >= E) return;
    int s = src[i], t = tgt[i];
    const float4* av = (const float4*)(g_attn + (size_t)s * H);
    float4 a0 = av[0], a1 = av[1];
    const uint4* mv = (const uint4*)(g_m + (size_t)t * H);
    uint4 m0 = mv[0], m1 = mv[1];
    float4 d0 = drop4[(size_t)i * 2], d1 = drop4[(size_t)i * 2 + 1];
    float4 o0, o1;
    o0.x = __expf(a0.x - key2f(m0.x)) * d0.x;
    o0.y = __expf(a0.y - key2f(m0.y)) * d0.y;
    o0.z = __expf(a0.z - key2f(m0.z)) * d0.z;
    o0.w = __expf(a0.w - key2f(m0.w)) * d0.w;
    o1.x = __expf(a1.x - key2f(m1.x)) * d1.x;
    o1.y = __expf(a1.y - key2f(m1.y)) * d1.y;
    o1.z = __expf(a1.z - key2f(m1.z)) * d1.z;
    o1.w = __expf(a1.w - key2f(m1.w)) * d1.w;
    out4[(size_t)i * 2]     = o0;
    out4[(size_t)i * 2 + 1] = o1;
}

// Inputs (metadata order): 0:X(f32) 1:attn_kernel(f32 D*H) 2:targets(i32 E)
// 3:sources(i32 E) 4:degree(f32 N, unused) 5:drop_mask(f32 E*H) 6:N.
extern "C" void kernel_launch(void* const* d_in, const int* in_sizes, int n_in,
                              void* d_out, int out_size) {
    const float4* X4   = (const float4*)d_in[0];
    const float*  Wk   = (const float*)d_in[1];
    const int*    tgt  = (const int*)d_in[2];
    const int*    srcs = (const int*)d_in[3];
    const float4* drop = (const float4*)d_in[5];
    float4*       out  = (float4*)d_out;

    const int E = in_sizes[2];
    const int N = in_sizes[4];

    // K1: 1184 blocks x 256 thr = 9472 warps, grid-stride over N rows.
    const int k1_blocks = 1184;
    k1_attn<<<k1_blocks, 256>>>(X4, Wk, N, k1_blocks * (256 / 32));

    const int block = 256;
    const int grid  = (E + block - 1) / block;
    k2_max<<<grid, block>>>(srcs, tgt, E);
    k3_out<<<grid, block>>>(srcs, tgt, drop, out, E);
}